// round 1
// baseline (speedup 1.0000x reference)
#include <cuda_runtime.h>

#define Bc 4
#define Nc 8192
#define NPc 2048
#define NSc 32
#define CINc 128
#define COUTc 256

// Scratch (no cudaMalloc allowed): device globals
__device__ int   g_fidx[Bc * NPc];
__device__ float g_featsT[(size_t)Bc * Nc * CINc];    // [B, N, CIN]  16 MB
__device__ float g_pooledT[(size_t)Bc * NPc * CINc];  // [B, NP, CIN]  4 MB

// ---------------------------------------------------------------------------
// 1) Furthest point sampling: one 1024-thread block per batch, 8 pts/thread
//    held in registers. Per iteration: fused min-update + local argmax, then
//    warp-shuffle + cross-warp shared reduction (lowest-index tie break).
// ---------------------------------------------------------------------------
__global__ void __launch_bounds__(1024, 1) fps_kernel(const float* __restrict__ xyz) {
    const int b = blockIdx.x;
    const float* xb = xyz + (size_t)b * Nc * 3;
    const int t = threadIdx.x;

    __shared__ float sv[32];
    __shared__ int   si[32];
    __shared__ int   sbest;

    float px[8], py[8], pz[8], mind[8];
    {
        float f[24];
        const float4* src = reinterpret_cast<const float4*>(xb + (size_t)t * 24);
#pragma unroll
        for (int i = 0; i < 6; i++) reinterpret_cast<float4*>(f)[i] = src[i];
#pragma unroll
        for (int p = 0; p < 8; p++) { px[p] = f[3*p]; py[p] = f[3*p+1]; pz[p] = f[3*p+2]; }
    }

    // init: distances to point 0, track local argmax
    float qx = xb[0], qy = xb[1], qz = xb[2];
    float bv = -1.0f; int bi = t * 8;
#pragma unroll
    for (int p = 0; p < 8; p++) {
        float dx = px[p] - qx, dy = py[p] - qy, dz = pz[p] - qz;
        float d = dx * dx; d = fmaf(dy, dy, d); d = fmaf(dz, dz, d);
        mind[p] = d;
        if (d > bv) { bv = d; bi = t * 8 + p; }
    }
    if (t == 0) g_fidx[b * NPc] = 0;

    for (int k = 1; k < NPc; k++) {
        // warp-level argmax reduce (value primary, lower index on tie)
        float v = bv; int ii = bi;
#pragma unroll
        for (int d = 16; d > 0; d >>= 1) {
            float ov = __shfl_xor_sync(0xffffffffu, v, d);
            int   oi = __shfl_xor_sync(0xffffffffu, ii, d);
            if (ov > v || (ov == v && oi < ii)) { v = ov; ii = oi; }
        }
        if ((t & 31) == 0) { sv[t >> 5] = v; si[t >> 5] = ii; }
        __syncthreads();
        if (t < 32) {
            v = sv[t]; ii = si[t];
#pragma unroll
            for (int d = 16; d > 0; d >>= 1) {
                float ov = __shfl_xor_sync(0xffffffffu, v, d);
                int   oi = __shfl_xor_sync(0xffffffffu, ii, d);
                if (ov > v || (ov == v && oi < ii)) { v = ov; ii = oi; }
            }
            if (t == 0) { sbest = ii; g_fidx[b * NPc + k] = ii; }
        }
        __syncthreads();

        const int w = sbest;
        qx = xb[w * 3]; qy = xb[w * 3 + 1]; qz = xb[w * 3 + 2];

        // fused min-update + local argmax for next iteration
        bv = -1.0f; bi = t * 8;
#pragma unroll
        for (int p = 0; p < 8; p++) {
            float dx = px[p] - qx, dy = py[p] - qy, dz = pz[p] - qz;
            float d = dx * dx; d = fmaf(dy, dy, d); d = fmaf(dz, dz, d);
            float mp = fminf(mind[p], d);
            mind[p] = mp;
            if (mp > bv) { bv = mp; bi = t * 8 + p; }
        }
    }
}

// ---------------------------------------------------------------------------
// 2) Transpose feats [B, CIN, N] -> featsT [B, N, CIN] for coalesced gathers
// ---------------------------------------------------------------------------
__global__ void __launch_bounds__(256) transpose_kernel(const float* __restrict__ feats) {
    __shared__ float tile[32][33];
    const int b  = blockIdx.z;
    const int n0 = blockIdx.x * 32;
    const int c0 = blockIdx.y * 32;
    const int x = threadIdx.x, y = threadIdx.y;
#pragma unroll
    for (int r = 0; r < 32; r += 8)
        tile[y + r][x] = feats[(size_t)(b * CINc + c0 + y + r) * Nc + n0 + x];
    __syncthreads();
#pragma unroll
    for (int r = 0; r < 32; r += 8)
        g_featsT[(size_t)(b * Nc + n0 + y + r) * CINc + c0 + x] = tile[x][y + r];
}

// ---------------------------------------------------------------------------
// 3) Ball query (warp 0, ballot-compaction with early exit) + gather + maxpool
//    (128 channel-threads). One block per query point.
// ---------------------------------------------------------------------------
__global__ void __launch_bounds__(128) pool_kernel(const float* __restrict__ xyz) {
    const int b = blockIdx.x >> 11;     // / NPc
    const int j = blockIdx.x & (NPc - 1);
    __shared__ int sidx[NSc];
    const int tid = threadIdx.x;

    if (tid < 32) {
        const float* xb = xyz + (size_t)b * Nc * 3;
        const int fi = g_fidx[b * NPc + j];
        const float qx = xb[fi * 3], qy = xb[fi * 3 + 1], qz = xb[fi * 3 + 2];
        const float R2 = 0.04f;  // float(0.04): matches JAX weak-typed 0.2*0.2 promotion
        int count = 0;
        for (int base = 0; base < Nc && count < NSc; base += 32) {
            const int i = base + tid;
            float dx = xb[i * 3] - qx, dy = xb[i * 3 + 1] - qy, dz = xb[i * 3 + 2] - qz;
            float d = dx * dx; d = fmaf(dy, dy, d); d = fmaf(dz, dz, d);
            const bool in = d < R2;
            const unsigned m = __ballot_sync(0xffffffffu, in);
            const int pos = count + __popc(m & ((1u << tid) - 1u));
            if (in && pos < NSc) sidx[pos] = i;
            count += __popc(m);
        }
        __syncwarp();
        // pad with first neighbor (count >= 1 always: query pt is in its own ball)
        const int first = (count > 0) ? sidx[0] : 0;
        for (int s = count + tid; s < NSc; s += 32) sidx[s] = first;
    }
    __syncthreads();

    const float* ft = g_featsT + (size_t)b * Nc * CINc;
    const int c = tid;  // 128 threads == CIN channels
    float m = __int_as_float(0xff800000);  // -inf
#pragma unroll
    for (int s = 0; s < NSc; s++)
        m = fmaxf(m, ft[(size_t)sidx[s] * CINc + c]);
    g_pooledT[((size_t)(b * NPc + j)) * CINc + c] = m;
}

// ---------------------------------------------------------------------------
// 4) out[b,o,j] = lrelu( (W[o,:] . pooledT[b,j,:]) * inv[o] + (beta - rmean*inv)[o] )
//    64x64 shared-tiled SIMT GEMM, 4x4 per-thread microtile, float4 stores.
// ---------------------------------------------------------------------------
__global__ void __launch_bounds__(256) gemm_bn_relu_kernel(
    const float* __restrict__ W,
    const float* __restrict__ gamma, const float* __restrict__ beta,
    const float* __restrict__ rmean, const float* __restrict__ rvar,
    float* __restrict__ out)
{
    __shared__ float Ws[64][33];
    __shared__ float Ps[64][33];
    const int b  = blockIdx.z;
    const int j0 = blockIdx.x * 64;
    const int o0 = blockIdx.y * 64;
    const int tid = threadIdx.x;
    const int tx = tid & 15, ty = tid >> 4;

    const float* Pbase = g_pooledT + ((size_t)b * NPc + j0) * CINc;

    float acc[4][4];
#pragma unroll
    for (int i = 0; i < 4; i++)
#pragma unroll
        for (int jj = 0; jj < 4; jj++) acc[i][jj] = 0.0f;

    for (int k0 = 0; k0 < CINc; k0 += 32) {
#pragma unroll
        for (int l = 0; l < 8; l++) {
            const int idx = tid + l * 256;
            const int r = idx >> 5, kk = idx & 31;
            Ws[r][kk] = W[(size_t)(o0 + r) * CINc + k0 + kk];
            Ps[r][kk] = Pbase[(size_t)r * CINc + k0 + kk];
        }
        __syncthreads();
#pragma unroll
        for (int k = 0; k < 32; k++) {
            const float a0 = Ws[ty * 4 + 0][k], a1 = Ws[ty * 4 + 1][k];
            const float a2 = Ws[ty * 4 + 2][k], a3 = Ws[ty * 4 + 3][k];
            const float p0 = Ps[tx * 4 + 0][k], p1 = Ps[tx * 4 + 1][k];
            const float p2 = Ps[tx * 4 + 2][k], p3 = Ps[tx * 4 + 3][k];
            acc[0][0] += a0 * p0; acc[0][1] += a0 * p1; acc[0][2] += a0 * p2; acc[0][3] += a0 * p3;
            acc[1][0] += a1 * p0; acc[1][1] += a1 * p1; acc[1][2] += a1 * p2; acc[1][3] += a1 * p3;
            acc[2][0] += a2 * p0; acc[2][1] += a2 * p1; acc[2][2] += a2 * p2; acc[2][3] += a2 * p3;
            acc[3][0] += a3 * p0; acc[3][1] += a3 * p1; acc[3][2] += a3 * p2; acc[3][3] += a3 * p3;
        }
        __syncthreads();
    }

#pragma unroll
    for (int oi = 0; oi < 4; oi++) {
        const int o = o0 + ty * 4 + oi;
        const float inv  = gamma[o] / sqrtf(rvar[o] + 1e-5f);
        const float bias = fmaf(-rmean[o], inv, beta[o]);  // beta - rmean*inv
        float vs[4];
#pragma unroll
        for (int ji = 0; ji < 4; ji++) {
            const float y = fmaf(acc[oi][ji], inv, bias);
            vs[ji] = (y >= 0.0f) ? y : 0.2f * y;
        }
        float4 vv = make_float4(vs[0], vs[1], vs[2], vs[3]);
        *reinterpret_cast<float4*>(out + (size_t)(b * COUTc + o) * NPc + j0 + tx * 4) = vv;
    }
}

// ---------------------------------------------------------------------------
extern "C" void kernel_launch(void* const* d_in, const int* in_sizes, int n_in,
                              void* d_out, int out_size) {
    const float* xyz    = (const float*)d_in[0];
    const float* feats  = (const float*)d_in[1];
    const float* conv_w = (const float*)d_in[2];
    const float* gamma  = (const float*)d_in[3];
    const float* beta   = (const float*)d_in[4];
    const float* rmean  = (const float*)d_in[5];
    const float* rvar   = (const float*)d_in[6];
    float* out = (float*)d_out;

    transpose_kernel<<<dim3(Nc / 32, CINc / 32, Bc), dim3(32, 8)>>>(feats);
    fps_kernel<<<Bc, 1024>>>(xyz);
    pool_kernel<<<Bc * NPc, 128>>>(xyz);
    gemm_bn_relu_kernel<<<dim3(NPc / 64, COUTc / 64, Bc), 256>>>(
        conv_w, gamma, beta, rmean, rvar, out);
}

// round 2
// speedup vs baseline: 1.0652x; 1.0652x over previous
#include <cuda_runtime.h>

#define Bc 4
#define Nc 8192
#define NPc 2048
#define NSc 32
#define CINc 128
#define COUTc 256

// Scratch (no cudaMalloc allowed): device globals
__device__ int   g_fidx[Bc * NPc];
__device__ float g_featsT[(size_t)Bc * Nc * CINc];    // [B, N, CIN]  16 MB
__device__ float g_pooledT[(size_t)Bc * NPc * CINc];  // [B, NP, CIN]  4 MB

// ---------------- packed f32x2 helpers (sm_103a) ----------------
typedef unsigned long long ull;

__device__ __forceinline__ ull f2pack(float lo, float hi) {
    ull r; asm("mov.b64 %0, {%1, %2};" : "=l"(r) : "f"(lo), "f"(hi)); return r;
}
__device__ __forceinline__ float2 f2unpack(ull v) {
    float2 f; asm("mov.b64 {%0, %1}, %2;" : "=f"(f.x), "=f"(f.y) : "l"(v)); return f;
}
__device__ __forceinline__ ull f2add(ull a, ull b) {
    ull r; asm("add.rn.f32x2 %0, %1, %2;" : "=l"(r) : "l"(a), "l"(b)); return r;
}
__device__ __forceinline__ ull f2mul(ull a, ull b) {
    ull r; asm("mul.rn.f32x2 %0, %1, %2;" : "=l"(r) : "l"(a), "l"(b)); return r;
}
__device__ __forceinline__ ull f2fma(ull a, ull b, ull c) {
    ull r; asm("fma.rn.f32x2 %0, %1, %2, %3;" : "=l"(r) : "l"(a), "l"(b), "l"(c)); return r;
}

// ---------------------------------------------------------------------------
// 1) Furthest point sampling: one 1024-thread block per batch, 8 pts/thread
//    in registers as packed f32x2 pairs. Per iteration:
//      - packed (p-q)^2 update + fmin (bit-identical per-lane to scalar form)
//      - post-loop fmax tree -> warp REDUX.MAX on value bits
//      - matched lanes atomicMin a 64-bit (~value_bits, index) key in shared
//        -> max value, lowest index tie-break, single __syncthreads per iter.
//    3-slot rotating key buffer: the reset of slot (k+2)%3 at iter k drains at
//    the next barrier, strictly before that slot's reuse at iter k+2 (race-free).
// ---------------------------------------------------------------------------
__global__ void __launch_bounds__(1024, 1) fps_kernel(const float* __restrict__ xyz) {
    const int b = blockIdx.x;
    const float* xb = xyz + (size_t)b * Nc * 3;
    const int t = threadIdx.x;

    __shared__ ull skey[3];

    ull pxp[4], pyp[4], pzp[4];
    float mind[8];
    {
        float f[24];
        const float4* src = reinterpret_cast<const float4*>(xb + (size_t)t * 24);
#pragma unroll
        for (int i = 0; i < 6; i++) reinterpret_cast<float4*>(f)[i] = src[i];
#pragma unroll
        for (int i = 0; i < 4; i++) {
            pxp[i] = f2pack(f[6 * i + 0], f[6 * i + 3]);
            pyp[i] = f2pack(f[6 * i + 1], f[6 * i + 4]);
            pzp[i] = f2pack(f[6 * i + 2], f[6 * i + 5]);
        }
    }

    // init: distances to point 0
    {
        const float qx = xb[0], qy = xb[1], qz = xb[2];
        const ull nqx = f2pack(-qx, -qx), nqy = f2pack(-qy, -qy), nqz = f2pack(-qz, -qz);
#pragma unroll
        for (int i = 0; i < 4; i++) {
            ull dx = f2add(pxp[i], nqx);
            ull dy = f2add(pyp[i], nqy);
            ull dz = f2add(pzp[i], nqz);
            ull d = f2mul(dx, dx); d = f2fma(dy, dy, d); d = f2fma(dz, dz, d);
            float2 dd = f2unpack(d);
            mind[2 * i] = dd.x; mind[2 * i + 1] = dd.y;
        }
    }
    if (t == 1023) {
        g_fidx[b * NPc] = 0;
        skey[0] = ~0ull; skey[1] = ~0ull; skey[2] = ~0ull;
    }
    __syncthreads();

    int s = 1;  // slot for k=1
    for (int k = 1; k < NPc; k++) {
        // local max over the 8 running minima (exact)
        float m0 = fmaxf(mind[0], mind[1]);
        float m1 = fmaxf(mind[2], mind[3]);
        float m2 = fmaxf(mind[4], mind[5]);
        float m3 = fmaxf(mind[6], mind[7]);
        m0 = fmaxf(m0, m1); m2 = fmaxf(m2, m3);
        const float bv = fmaxf(m0, m2);

        // warp max on value bits (distances >= 0: uint order == float order)
        const unsigned best = __reduce_max_sync(0xffffffffu, __float_as_uint(bv));

        // lanes holding the warp max publish (max-value, lowest-index) key
        unsigned msk = 0u;
#pragma unroll
        for (int p = 0; p < 8; p++)
            msk |= (__float_as_uint(mind[p]) == best) ? (1u << p) : 0u;
        if (msk) {
            const unsigned idx = (unsigned)(t * 8) + (unsigned)(__ffs(msk) - 1);
            atomicMin(&skey[s], ((ull)(~best) << 32) | (ull)idx);
        }
        __syncthreads();

        const int w = (int)(unsigned)skey[s];
        // rotate: reset slot (k+2)%3 — reused at iter k+2, drains at next barrier
        int s2 = s + 2; if (s2 >= 3) s2 -= 3;
        if (t == 1023) { skey[s2] = ~0ull; g_fidx[b * NPc + k] = w; }
        if (++s == 3) s = 0;

        // broadcast load of winner coords (L1-resident, same-address broadcast)
        const float qx = xb[w * 3], qy = xb[w * 3 + 1], qz = xb[w * 3 + 2];
        const ull nqx = f2pack(-qx, -qx), nqy = f2pack(-qy, -qy), nqz = f2pack(-qz, -qz);
#pragma unroll
        for (int i = 0; i < 4; i++) {
            ull dx = f2add(pxp[i], nqx);
            ull dy = f2add(pyp[i], nqy);
            ull dz = f2add(pzp[i], nqz);
            ull d = f2mul(dx, dx); d = f2fma(dy, dy, d); d = f2fma(dz, dz, d);
            float2 dd = f2unpack(d);
            mind[2 * i]     = fminf(mind[2 * i],     dd.x);
            mind[2 * i + 1] = fminf(mind[2 * i + 1], dd.y);
        }
    }
}

// ---------------------------------------------------------------------------
// 2) Transpose feats [B, CIN, N] -> featsT [B, N, CIN] for coalesced gathers
// ---------------------------------------------------------------------------
__global__ void __launch_bounds__(256) transpose_kernel(const float* __restrict__ feats) {
    __shared__ float tile[32][33];
    const int b  = blockIdx.z;
    const int n0 = blockIdx.x * 32;
    const int c0 = blockIdx.y * 32;
    const int x = threadIdx.x, y = threadIdx.y;
#pragma unroll
    for (int r = 0; r < 32; r += 8)
        tile[y + r][x] = feats[(size_t)(b * CINc + c0 + y + r) * Nc + n0 + x];
    __syncthreads();
#pragma unroll
    for (int r = 0; r < 32; r += 8)
        g_featsT[(size_t)(b * Nc + n0 + y + r) * CINc + c0 + x] = tile[x][y + r];
}

// ---------------------------------------------------------------------------
// 3) Ball query (warp 0, ballot-compaction with early exit) + gather + maxpool
//    (128 channel-threads). One block per query point.
// ---------------------------------------------------------------------------
__global__ void __launch_bounds__(128) pool_kernel(const float* __restrict__ xyz) {
    const int b = blockIdx.x >> 11;     // / NPc
    const int j = blockIdx.x & (NPc - 1);
    __shared__ int sidx[NSc];
    const int tid = threadIdx.x;

    if (tid < 32) {
        const float* xb = xyz + (size_t)b * Nc * 3;
        const int fi = g_fidx[b * NPc + j];
        const float qx = xb[fi * 3], qy = xb[fi * 3 + 1], qz = xb[fi * 3 + 2];
        const float R2 = 0.04f;  // float(0.04): matches JAX weak-typed 0.2*0.2 promotion
        int count = 0;
        for (int base = 0; base < Nc && count < NSc; base += 32) {
            const int i = base + tid;
            float dx = xb[i * 3] - qx, dy = xb[i * 3 + 1] - qy, dz = xb[i * 3 + 2] - qz;
            float d = dx * dx; d = fmaf(dy, dy, d); d = fmaf(dz, dz, d);
            const bool in = d < R2;
            const unsigned m = __ballot_sync(0xffffffffu, in);
            const int pos = count + __popc(m & ((1u << tid) - 1u));
            if (in && pos < NSc) sidx[pos] = i;
            count += __popc(m);
        }
        __syncwarp();
        // pad with first neighbor (count >= 1 always: query pt is in its own ball)
        const int first = (count > 0) ? sidx[0] : 0;
        for (int s = count + tid; s < NSc; s += 32) sidx[s] = first;
    }
    __syncthreads();

    const float* ft = g_featsT + (size_t)b * Nc * CINc;
    const int c = tid;  // 128 threads == CIN channels
    float m = __int_as_float(0xff800000);  // -inf
#pragma unroll
    for (int s = 0; s < NSc; s++)
        m = fmaxf(m, ft[(size_t)sidx[s] * CINc + c]);
    g_pooledT[((size_t)(b * NPc + j)) * CINc + c] = m;
}

// ---------------------------------------------------------------------------
// 4) out[b,o,j] = lrelu( (W[o,:] . pooledT[b,j,:]) * inv[o] + (beta - rmean*inv)[o] )
//    64x64 shared-tiled SIMT GEMM, 4x4 per-thread microtile, float4 stores.
// ---------------------------------------------------------------------------
__global__ void __launch_bounds__(256) gemm_bn_relu_kernel(
    const float* __restrict__ W,
    const float* __restrict__ gamma, const float* __restrict__ beta,
    const float* __restrict__ rmean, const float* __restrict__ rvar,
    float* __restrict__ out)
{
    __shared__ float Ws[64][33];
    __shared__ float Ps[64][33];
    const int b  = blockIdx.z;
    const int j0 = blockIdx.x * 64;
    const int o0 = blockIdx.y * 64;
    const int tid = threadIdx.x;
    const int tx = tid & 15, ty = tid >> 4;

    const float* Pbase = g_pooledT + ((size_t)b * NPc + j0) * CINc;

    float acc[4][4];
#pragma unroll
    for (int i = 0; i < 4; i++)
#pragma unroll
        for (int jj = 0; jj < 4; jj++) acc[i][jj] = 0.0f;

    for (int k0 = 0; k0 < CINc; k0 += 32) {
#pragma unroll
        for (int l = 0; l < 8; l++) {
            const int idx = tid + l * 256;
            const int r = idx >> 5, kk = idx & 31;
            Ws[r][kk] = W[(size_t)(o0 + r) * CINc + k0 + kk];
            Ps[r][kk] = Pbase[(size_t)r * CINc + k0 + kk];
        }
        __syncthreads();
#pragma unroll
        for (int k = 0; k < 32; k++) {
            const float a0 = Ws[ty * 4 + 0][k], a1 = Ws[ty * 4 + 1][k];
            const float a2 = Ws[ty * 4 + 2][k], a3 = Ws[ty * 4 + 3][k];
            const float p0 = Ps[tx * 4 + 0][k], p1 = Ps[tx * 4 + 1][k];
            const float p2 = Ps[tx * 4 + 2][k], p3 = Ps[tx * 4 + 3][k];
            acc[0][0] += a0 * p0; acc[0][1] += a0 * p1; acc[0][2] += a0 * p2; acc[0][3] += a0 * p3;
            acc[1][0] += a1 * p0; acc[1][1] += a1 * p1; acc[1][2] += a1 * p2; acc[1][3] += a1 * p3;
            acc[2][0] += a2 * p0; acc[2][1] += a2 * p1; acc[2][2] += a2 * p2; acc[2][3] += a2 * p3;
            acc[3][0] += a3 * p0; acc[3][1] += a3 * p1; acc[3][2] += a3 * p2; acc[3][3] += a3 * p3;
        }
        __syncthreads();
    }

#pragma unroll
    for (int oi = 0; oi < 4; oi++) {
        const int o = o0 + ty * 4 + oi;
        const float inv  = gamma[o] / sqrtf(rvar[o] + 1e-5f);
        const float bias = fmaf(-rmean[o], inv, beta[o]);  // beta - rmean*inv
        float vs[4];
#pragma unroll
        for (int ji = 0; ji < 4; ji++) {
            const float y = fmaf(acc[oi][ji], inv, bias);
            vs[ji] = (y >= 0.0f) ? y : 0.2f * y;
        }
        float4 vv = make_float4(vs[0], vs[1], vs[2], vs[3]);
        *reinterpret_cast<float4*>(out + (size_t)(b * COUTc + o) * NPc + j0 + tx * 4) = vv;
    }
}

// ---------------------------------------------------------------------------
extern "C" void kernel_launch(void* const* d_in, const int* in_sizes, int n_in,
                              void* d_out, int out_size) {
    const float* xyz    = (const float*)d_in[0];
    const float* feats  = (const float*)d_in[1];
    const float* conv_w = (const float*)d_in[2];
    const float* gamma  = (const float*)d_in[3];
    const float* beta   = (const float*)d_in[4];
    const float* rmean  = (const float*)d_in[5];
    const float* rvar   = (const float*)d_in[6];
    float* out = (float*)d_out;

    transpose_kernel<<<dim3(Nc / 32, CINc / 32, Bc), dim3(32, 8)>>>(feats);
    fps_kernel<<<Bc, 1024>>>(xyz);
    pool_kernel<<<Bc * NPc, 128>>>(xyz);
    gemm_bn_relu_kernel<<<dim3(NPc / 64, COUTc / 64, Bc), 256>>>(
        conv_w, gamma, beta, rmean, rvar, out);
}

// round 3
// speedup vs baseline: 1.4068x; 1.3208x over previous
#include <cuda_runtime.h>

#define Bc 4
#define Nc 8192
#define NPc 2048
#define NSc 32
#define CINc 128
#define COUTc 256

// Scratch (no cudaMalloc allowed): device globals
__device__ int   g_fidx[Bc * NPc];
__device__ float g_featsT[(size_t)Bc * Nc * CINc];    // [B, N, CIN]  16 MB
__device__ float g_pooledT[(size_t)Bc * NPc * CINc];  // [B, NP, CIN]  4 MB

// ---------------- packed f32x2 helpers (sm_103a) ----------------
typedef unsigned long long ull;

__device__ __forceinline__ ull f2pack(float lo, float hi) {
    ull r; asm("mov.b64 %0, {%1, %2};" : "=l"(r) : "f"(lo), "f"(hi)); return r;
}
__device__ __forceinline__ float2 f2unpack(ull v) {
    float2 f; asm("mov.b64 {%0, %1}, %2;" : "=f"(f.x), "=f"(f.y) : "l"(v)); return f;
}
__device__ __forceinline__ ull f2add(ull a, ull b) {
    ull r; asm("add.rn.f32x2 %0, %1, %2;" : "=l"(r) : "l"(a), "l"(b)); return r;
}
__device__ __forceinline__ ull f2mul(ull a, ull b) {
    ull r; asm("mul.rn.f32x2 %0, %1, %2;" : "=l"(r) : "l"(a), "l"(b)); return r;
}
__device__ __forceinline__ ull f2fma(ull a, ull b, ull c) {
    ull r; asm("fma.rn.f32x2 %0, %1, %2, %3;" : "=l"(r) : "l"(a), "l"(b), "l"(c)); return r;
}

// ---------------------------------------------------------------------------
// 1) Furthest point sampling: one 1024-thread block per batch, 8 pts/thread
//    in registers as packed f32x2 pairs. Per iteration:
//      - packed (p-q)^2 update + fmin (bit-identical per-lane to scalar form)
//      - stage 1: warp REDUX.MAX on value bits + REDUX.MIN on matching index;
//        lane 0 stores the warp's (value, min-index) pair to shared
//      - ONE __syncthreads
//      - stage 2: ALL warps redundantly reduce the 32 pairs (REDUX.MAX value,
//        REDUX.MIN matching index) -> every thread gets the global winner.
//        No atomics, no broadcast variable, no second barrier.
//    Shared pairs are double-buffered by iteration parity: a store to buffer
//    (k&1) at iter k+2 is separated from any read of that buffer at iter k by
//    the barrier at iter k+1 (race-free).
//    Tie-break = lowest global index (warp ranges contiguous ascending).
// ---------------------------------------------------------------------------
__global__ void __launch_bounds__(1024, 1) fps_kernel(const float* __restrict__ xyz) {
    const int b = blockIdx.x;
    const float* xb = xyz + (size_t)b * Nc * 3;
    const int t = threadIdx.x;
    const int lane = t & 31;

    __shared__ unsigned sv[2][32];
    __shared__ int      si[2][32];

    ull pxp[4], pyp[4], pzp[4];
    float mind[8];
    {
        float f[24];
        const float4* src = reinterpret_cast<const float4*>(xb + (size_t)t * 24);
#pragma unroll
        for (int i = 0; i < 6; i++) reinterpret_cast<float4*>(f)[i] = src[i];
#pragma unroll
        for (int i = 0; i < 4; i++) {
            pxp[i] = f2pack(f[6 * i + 0], f[6 * i + 3]);
            pyp[i] = f2pack(f[6 * i + 1], f[6 * i + 4]);
            pzp[i] = f2pack(f[6 * i + 2], f[6 * i + 5]);
        }
    }

    // init: distances to point 0
    {
        const float qx = xb[0], qy = xb[1], qz = xb[2];
        const ull nqx = f2pack(-qx, -qx), nqy = f2pack(-qy, -qy), nqz = f2pack(-qz, -qz);
#pragma unroll
        for (int i = 0; i < 4; i++) {
            ull dx = f2add(pxp[i], nqx);
            ull dy = f2add(pyp[i], nqy);
            ull dz = f2add(pzp[i], nqz);
            ull d = f2mul(dx, dx); d = f2fma(dy, dy, d); d = f2fma(dz, dz, d);
            float2 dd = f2unpack(d);
            mind[2 * i] = dd.x; mind[2 * i + 1] = dd.y;
        }
    }
    if (t == 0) g_fidx[b * NPc] = 0;

    for (int k = 1; k < NPc; k++) {
        // local max over the 8 running minima (exact)
        float m0 = fmaxf(mind[0], mind[1]);
        float m1 = fmaxf(mind[2], mind[3]);
        float m2 = fmaxf(mind[4], mind[5]);
        float m3 = fmaxf(mind[6], mind[7]);
        m0 = fmaxf(m0, m1); m2 = fmaxf(m2, m3);
        const float bv = fmaxf(m0, m2);

        // stage 1: warp max value (distances >= 0: uint order == float order)
        const unsigned best = __reduce_max_sync(0xffffffffu, __float_as_uint(bv));
        unsigned msk = 0u;
#pragma unroll
        for (int p = 0; p < 8; p++)
            msk |= (__float_as_uint(mind[p]) == best) ? (1u << p) : 0u;
        const int cand = msk ? (t * 8 + __ffs(msk) - 1) : 0x7fffffff;
        const int widx = __reduce_min_sync(0xffffffffu, cand);

        const int s = k & 1;
        if (lane == 0) { sv[s][t >> 5] = best; si[s][t >> 5] = widx; }
        __syncthreads();

        // stage 2: all warps redundantly reduce the 32 (value, index) pairs
        const unsigned wv = sv[s][lane];
        const int      wi = si[s][lane];
        const unsigned gbest = __reduce_max_sync(0xffffffffu, wv);
        const int gcand = (wv == gbest) ? wi : 0x7fffffff;
        const int w = __reduce_min_sync(0xffffffffu, gcand);
        if (t == 0) g_fidx[b * NPc + k] = w;

        // broadcast load of winner coords (L1-resident, same-address broadcast)
        const float qx = xb[w * 3], qy = xb[w * 3 + 1], qz = xb[w * 3 + 2];
        const ull nqx = f2pack(-qx, -qx), nqy = f2pack(-qy, -qy), nqz = f2pack(-qz, -qz);
#pragma unroll
        for (int i = 0; i < 4; i++) {
            ull dx = f2add(pxp[i], nqx);
            ull dy = f2add(pyp[i], nqy);
            ull dz = f2add(pzp[i], nqz);
            ull d = f2mul(dx, dx); d = f2fma(dy, dy, d); d = f2fma(dz, dz, d);
            float2 dd = f2unpack(d);
            mind[2 * i]     = fminf(mind[2 * i],     dd.x);
            mind[2 * i + 1] = fminf(mind[2 * i + 1], dd.y);
        }
    }
}

// ---------------------------------------------------------------------------
// 2) Transpose feats [B, CIN, N] -> featsT [B, N, CIN] for coalesced gathers
// ---------------------------------------------------------------------------
__global__ void __launch_bounds__(256) transpose_kernel(const float* __restrict__ feats) {
    __shared__ float tile[32][33];
    const int b  = blockIdx.z;
    const int n0 = blockIdx.x * 32;
    const int c0 = blockIdx.y * 32;
    const int x = threadIdx.x, y = threadIdx.y;
#pragma unroll
    for (int r = 0; r < 32; r += 8)
        tile[y + r][x] = feats[(size_t)(b * CINc + c0 + y + r) * Nc + n0 + x];
    __syncthreads();
#pragma unroll
    for (int r = 0; r < 32; r += 8)
        g_featsT[(size_t)(b * Nc + n0 + y + r) * CINc + c0 + x] = tile[x][y + r];
}

// ---------------------------------------------------------------------------
// 3) Ball query (warp 0, ballot-compaction with early exit) + gather + maxpool
//    (128 channel-threads). One block per query point.
// ---------------------------------------------------------------------------
__global__ void __launch_bounds__(128) pool_kernel(const float* __restrict__ xyz) {
    const int b = blockIdx.x >> 11;     // / NPc
    const int j = blockIdx.x & (NPc - 1);
    __shared__ int sidx[NSc];
    const int tid = threadIdx.x;

    if (tid < 32) {
        const float* xb = xyz + (size_t)b * Nc * 3;
        const int fi = g_fidx[b * NPc + j];
        const float qx = xb[fi * 3], qy = xb[fi * 3 + 1], qz = xb[fi * 3 + 2];
        const float R2 = 0.04f;  // float(0.04): matches JAX weak-typed 0.2*0.2 promotion
        int count = 0;
        for (int base = 0; base < Nc && count < NSc; base += 32) {
            const int i = base + tid;
            float dx = xb[i * 3] - qx, dy = xb[i * 3 + 1] - qy, dz = xb[i * 3 + 2] - qz;
            float d = dx * dx; d = fmaf(dy, dy, d); d = fmaf(dz, dz, d);
            const bool in = d < R2;
            const unsigned m = __ballot_sync(0xffffffffu, in);
            const int pos = count + __popc(m & ((1u << tid) - 1u));
            if (in && pos < NSc) sidx[pos] = i;
            count += __popc(m);
        }
        __syncwarp();
        // pad with first neighbor (count >= 1 always: query pt is in its own ball)
        const int first = (count > 0) ? sidx[0] : 0;
        for (int s = count + tid; s < NSc; s += 32) sidx[s] = first;
    }
    __syncthreads();

    const float* ft = g_featsT + (size_t)b * Nc * CINc;
    const int c = tid;  // 128 threads == CIN channels
    float m = __int_as_float(0xff800000);  // -inf
#pragma unroll
    for (int s = 0; s < NSc; s++)
        m = fmaxf(m, ft[(size_t)sidx[s] * CINc + c]);
    g_pooledT[((size_t)(b * NPc + j)) * CINc + c] = m;
}

// ---------------------------------------------------------------------------
// 4) out[b,o,j] = lrelu( (W[o,:] . pooledT[b,j,:]) * inv[o] + (beta - rmean*inv)[o] )
//    64x64 shared-tiled SIMT GEMM, 4x4 per-thread microtile, float4 stores.
// ---------------------------------------------------------------------------
__global__ void __launch_bounds__(256) gemm_bn_relu_kernel(
    const float* __restrict__ W,
    const float* __restrict__ gamma, const float* __restrict__ beta,
    const float* __restrict__ rmean, const float* __restrict__ rvar,
    float* __restrict__ out)
{
    __shared__ float Ws[64][33];
    __shared__ float Ps[64][33];
    const int b  = blockIdx.z;
    const int j0 = blockIdx.x * 64;
    const int o0 = blockIdx.y * 64;
    const int tid = threadIdx.x;
    const int tx = tid & 15, ty = tid >> 4;

    const float* Pbase = g_pooledT + ((size_t)b * NPc + j0) * CINc;

    float acc[4][4];
#pragma unroll
    for (int i = 0; i < 4; i++)
#pragma unroll
        for (int jj = 0; jj < 4; jj++) acc[i][jj] = 0.0f;

    for (int k0 = 0; k0 < CINc; k0 += 32) {
#pragma unroll
        for (int l = 0; l < 8; l++) {
            const int idx = tid + l * 256;
            const int r = idx >> 5, kk = idx & 31;
            Ws[r][kk] = W[(size_t)(o0 + r) * CINc + k0 + kk];
            Ps[r][kk] = Pbase[(size_t)r * CINc + k0 + kk];
        }
        __syncthreads();
#pragma unroll
        for (int k = 0; k < 32; k++) {
            const float a0 = Ws[ty * 4 + 0][k], a1 = Ws[ty * 4 + 1][k];
            const float a2 = Ws[ty * 4 + 2][k], a3 = Ws[ty * 4 + 3][k];
            const float p0 = Ps[tx * 4 + 0][k], p1 = Ps[tx * 4 + 1][k];
            const float p2 = Ps[tx * 4 + 2][k], p3 = Ps[tx * 4 + 3][k];
            acc[0][0] += a0 * p0; acc[0][1] += a0 * p1; acc[0][2] += a0 * p2; acc[0][3] += a0 * p3;
            acc[1][0] += a1 * p0; acc[1][1] += a1 * p1; acc[1][2] += a1 * p2; acc[1][3] += a1 * p3;
            acc[2][0] += a2 * p0; acc[2][1] += a2 * p1; acc[2][2] += a2 * p2; acc[2][3] += a2 * p3;
            acc[3][0] += a3 * p0; acc[3][1] += a3 * p1; acc[3][2] += a3 * p2; acc[3][3] += a3 * p3;
        }
        __syncthreads();
    }

#pragma unroll
    for (int oi = 0; oi < 4; oi++) {
        const int o = o0 + ty * 4 + oi;
        const float inv  = gamma[o] / sqrtf(rvar[o] + 1e-5f);
        const float bias = fmaf(-rmean[o], inv, beta[o]);  // beta - rmean*inv
        float vs[4];
#pragma unroll
        for (int ji = 0; ji < 4; ji++) {
            const float y = fmaf(acc[oi][ji], inv, bias);
            vs[ji] = (y >= 0.0f) ? y : 0.2f * y;
        }
        float4 vv = make_float4(vs[0], vs[1], vs[2], vs[3]);
        *reinterpret_cast<float4*>(out + (size_t)(b * COUTc + o) * NPc + j0 + tx * 4) = vv;
    }
}

// ---------------------------------------------------------------------------
extern "C" void kernel_launch(void* const* d_in, const int* in_sizes, int n_in,
                              void* d_out, int out_size) {
    const float* xyz    = (const float*)d_in[0];
    const float* feats  = (const float*)d_in[1];
    const float* conv_w = (const float*)d_in[2];
    const float* gamma  = (const float*)d_in[3];
    const float* beta   = (const float*)d_in[4];
    const float* rmean  = (const float*)d_in[5];
    const float* rvar   = (const float*)d_in[6];
    float* out = (float*)d_out;

    transpose_kernel<<<dim3(Nc / 32, CINc / 32, Bc), dim3(32, 8)>>>(feats);
    fps_kernel<<<Bc, 1024>>>(xyz);
    pool_kernel<<<Bc * NPc, 128>>>(xyz);
    gemm_bn_relu_kernel<<<dim3(NPc / 64, COUTc / 64, Bc), 256>>>(
        conv_w, gamma, beta, rmean, rvar, out);
}

// round 5
// speedup vs baseline: 1.4962x; 1.0635x over previous
#include <cuda_runtime.h>

#define Bc 4
#define Nc 8192
#define NPc 2048
#define NSc 32
#define CINc 128
#define COUTc 256

// Scratch (no cudaMalloc allowed): device globals
__device__ int   g_fidx[Bc * NPc];
__device__ float g_featsT[(size_t)Bc * Nc * CINc];    // [B, N, CIN]  16 MB
__device__ float g_pooledT[(size_t)Bc * NPc * CINc];  // [B, NP, CIN]  4 MB

// ---------------- packed f32x2 helpers (sm_103a) ----------------
// NOTE: only add/mul/fma exist in f32x2 form; min/max do NOT (ptxas rejects).
typedef unsigned long long ull;

__device__ __forceinline__ ull f2pack(float lo, float hi) {
    ull r; asm("mov.b64 %0, {%1, %2};" : "=l"(r) : "f"(lo), "f"(hi)); return r;
}
__device__ __forceinline__ float2 f2unpack(ull v) {
    float2 f; asm("mov.b64 {%0, %1}, %2;" : "=f"(f.x), "=f"(f.y) : "l"(v)); return f;
}
__device__ __forceinline__ ull f2add(ull a, ull b) {
    ull r; asm("add.rn.f32x2 %0, %1, %2;" : "=l"(r) : "l"(a), "l"(b)); return r;
}
__device__ __forceinline__ ull f2mul(ull a, ull b) {
    ull r; asm("mul.rn.f32x2 %0, %1, %2;" : "=l"(r) : "l"(a), "l"(b)); return r;
}
__device__ __forceinline__ ull f2fma(ull a, ull b, ull c) {
    ull r; asm("fma.rn.f32x2 %0, %1, %2, %3;" : "=l"(r) : "l"(a), "l"(b), "l"(c)); return r;
}

// ---------------------------------------------------------------------------
// 1) Furthest point sampling: one 512-thread block per batch, 16 pts/thread
//    (fatter threads amortize per-thread overhead; packed-arith floor is
//    thread-count invariant). Packed (p-q)^2 via f32x2; scalar fmin update
//    with FUSED scalar running max (no post-loop tree, no serial tail).
//    Per-lane arithmetic identical to the scalar formulation -> selected
//    indices bit-identical across rounds.
//    Reduction per iteration (one __syncthreads):
//      - stage 1: warp REDUX.MAX on value bits + REDUX.MIN on matching index;
//        lane 0 stores the warp's (value, min-index) pair to shared
//      - stage 2: ALL warps redundantly reduce the 16 pairs -> global winner.
//    Shared pairs double-buffered by iteration parity (race-free across the
//    single barrier). Tie-break = lowest global index (warp ranges ascending).
// ---------------------------------------------------------------------------
__global__ void __launch_bounds__(512, 1) fps_kernel(const float* __restrict__ xyz) {
    const int b = blockIdx.x;
    const float* xb = xyz + (size_t)b * Nc * 3;
    const int t = threadIdx.x;
    const int lane = t & 31;

    __shared__ unsigned sv[2][16];
    __shared__ int      si[2][16];

    ull pxp[8], pyp[8], pzp[8];
    float mind[16];
    {
        float f[48];
        const float4* src = reinterpret_cast<const float4*>(xb + (size_t)t * 48);
#pragma unroll
        for (int i = 0; i < 12; i++) reinterpret_cast<float4*>(f)[i] = src[i];
#pragma unroll
        for (int i = 0; i < 8; i++) {
            pxp[i] = f2pack(f[6 * i + 0], f[6 * i + 3]);
            pyp[i] = f2pack(f[6 * i + 1], f[6 * i + 4]);
            pzp[i] = f2pack(f[6 * i + 2], f[6 * i + 5]);
        }
    }

    float bv;  // running block-local max of mind
    {
        const float qx = xb[0], qy = xb[1], qz = xb[2];
        const ull nqx = f2pack(-qx, -qx), nqy = f2pack(-qy, -qy), nqz = f2pack(-qz, -qz);
        float rm = 0.0f;
#pragma unroll
        for (int i = 0; i < 8; i++) {
            ull dx = f2add(pxp[i], nqx);
            ull dy = f2add(pyp[i], nqy);
            ull dz = f2add(pzp[i], nqz);
            ull d = f2mul(dx, dx); d = f2fma(dy, dy, d); d = f2fma(dz, dz, d);
            const float2 dd = f2unpack(d);
            mind[2 * i]     = dd.x;
            mind[2 * i + 1] = dd.y;
            rm = fmaxf(rm, fmaxf(dd.x, dd.y));
        }
        bv = rm;
    }
    if (t == 0) g_fidx[b * NPc] = 0;

    for (int k = 1; k < NPc; k++) {
        // stage 1: warp max value (distances >= 0: uint order == float order)
        const unsigned best = __reduce_max_sync(0xffffffffu, __float_as_uint(bv));
        unsigned msk = 0u;
#pragma unroll
        for (int p = 0; p < 16; p++)
            msk |= (__float_as_uint(mind[p]) == best) ? (1u << p) : 0u;
        const int cand = msk ? (t * 16 + __ffs(msk) - 1) : 0x7fffffff;
        const int widx = __reduce_min_sync(0xffffffffu, cand);

        const int s = k & 1;
        if (lane == 0) { sv[s][t >> 5] = best; si[s][t >> 5] = widx; }
        __syncthreads();

        // stage 2: all warps redundantly reduce the 16 (value, index) pairs
        const unsigned wv = sv[s][lane & 15];
        const int      wi = si[s][lane & 15];
        const unsigned gbest = __reduce_max_sync(0xffffffffu, wv);
        const int gcand = (wv == gbest) ? wi : 0x7fffffff;
        const int w = __reduce_min_sync(0xffffffffu, gcand);
        if (t == 0) g_fidx[b * NPc + k] = w;

        // broadcast load of winner coords (L1-resident, same-address broadcast)
        const float qx = xb[w * 3], qy = xb[w * 3 + 1], qz = xb[w * 3 + 2];
        const ull nqx = f2pack(-qx, -qx), nqy = f2pack(-qy, -qy), nqz = f2pack(-qz, -qz);

        // packed distance + scalar min update + fused running max
        float rm = 0.0f;
#pragma unroll
        for (int i = 0; i < 8; i++) {
            ull dx = f2add(pxp[i], nqx);
            ull dy = f2add(pyp[i], nqy);
            ull dz = f2add(pzp[i], nqz);
            ull d = f2mul(dx, dx); d = f2fma(dy, dy, d); d = f2fma(dz, dz, d);
            const float2 dd = f2unpack(d);
            const float m0 = fminf(mind[2 * i],     dd.x);
            const float m1 = fminf(mind[2 * i + 1], dd.y);
            mind[2 * i]     = m0;
            mind[2 * i + 1] = m1;
            rm = fmaxf(rm, fmaxf(m0, m1));
        }
        bv = rm;
    }
}

// ---------------------------------------------------------------------------
// 2) Transpose feats [B, CIN, N] -> featsT [B, N, CIN] for coalesced gathers
// ---------------------------------------------------------------------------
__global__ void __launch_bounds__(256) transpose_kernel(const float* __restrict__ feats) {
    __shared__ float tile[32][33];
    const int b  = blockIdx.z;
    const int n0 = blockIdx.x * 32;
    const int c0 = blockIdx.y * 32;
    const int x = threadIdx.x, y = threadIdx.y;
#pragma unroll
    for (int r = 0; r < 32; r += 8)
        tile[y + r][x] = feats[(size_t)(b * CINc + c0 + y + r) * Nc + n0 + x];
    __syncthreads();
#pragma unroll
    for (int r = 0; r < 32; r += 8)
        g_featsT[(size_t)(b * Nc + n0 + y + r) * CINc + c0 + x] = tile[x][y + r];
}

// ---------------------------------------------------------------------------
// 3) Ball query (warp 0, ballot-compaction with early exit) + gather + maxpool
//    (128 channel-threads). One block per query point.
// ---------------------------------------------------------------------------
__global__ void __launch_bounds__(128) pool_kernel(const float* __restrict__ xyz) {
    const int b = blockIdx.x >> 11;     // / NPc
    const int j = blockIdx.x & (NPc - 1);
    __shared__ int sidx[NSc];
    const int tid = threadIdx.x;

    if (tid < 32) {
        const float* xb = xyz + (size_t)b * Nc * 3;
        const int fi = g_fidx[b * NPc + j];
        const float qx = xb[fi * 3], qy = xb[fi * 3 + 1], qz = xb[fi * 3 + 2];
        const float R2 = 0.04f;  // float(0.04): matches JAX weak-typed 0.2*0.2 promotion
        int count = 0;
        for (int base = 0; base < Nc && count < NSc; base += 32) {
            const int i = base + tid;
            float dx = xb[i * 3] - qx, dy = xb[i * 3 + 1] - qy, dz = xb[i * 3 + 2] - qz;
            float d = dx * dx; d = fmaf(dy, dy, d); d = fmaf(dz, dz, d);
            const bool in = d < R2;
            const unsigned m = __ballot_sync(0xffffffffu, in);
            const int pos = count + __popc(m & ((1u << tid) - 1u));
            if (in && pos < NSc) sidx[pos] = i;
            count += __popc(m);
        }
        __syncwarp();
        // pad with first neighbor (count >= 1 always: query pt is in its own ball)
        const int first = (count > 0) ? sidx[0] : 0;
        for (int s = count + tid; s < NSc; s += 32) sidx[s] = first;
    }
    __syncthreads();

    const float* ft = g_featsT + (size_t)b * Nc * CINc;
    const int c = tid;  // 128 threads == CIN channels
    float m = __int_as_float(0xff800000);  // -inf
#pragma unroll
    for (int s = 0; s < NSc; s++)
        m = fmaxf(m, ft[(size_t)sidx[s] * CINc + c]);
    g_pooledT[((size_t)(b * NPc + j)) * CINc + c] = m;
}

// ---------------------------------------------------------------------------
// 4) out[b,o,j] = lrelu( (W[o,:] . pooledT[b,j,:]) * inv[o] + (beta - rmean*inv)[o] )
//    64x64 shared-tiled SIMT GEMM, 4x4 per-thread microtile, float4 stores.
// ---------------------------------------------------------------------------
__global__ void __launch_bounds__(256) gemm_bn_relu_kernel(
    const float* __restrict__ W,
    const float* __restrict__ gamma, const float* __restrict__ beta,
    const float* __restrict__ rmean, const float* __restrict__ rvar,
    float* __restrict__ out)
{
    __shared__ float Ws[64][33];
    __shared__ float Ps[64][33];
    const int b  = blockIdx.z;
    const int j0 = blockIdx.x * 64;
    const int o0 = blockIdx.y * 64;
    const int tid = threadIdx.x;
    const int tx = tid & 15, ty = tid >> 4;

    const float* Pbase = g_pooledT + ((size_t)b * NPc + j0) * CINc;

    float acc[4][4];
#pragma unroll
    for (int i = 0; i < 4; i++)
#pragma unroll
        for (int jj = 0; jj < 4; jj++) acc[i][jj] = 0.0f;

    for (int k0 = 0; k0 < CINc; k0 += 32) {
#pragma unroll
        for (int l = 0; l < 8; l++) {
            const int idx = tid + l * 256;
            const int r = idx >> 5, kk = idx & 31;
            Ws[r][kk] = W[(size_t)(o0 + r) * CINc + k0 + kk];
            Ps[r][kk] = Pbase[(size_t)r * CINc + k0 + kk];
        }
        __syncthreads();
#pragma unroll
        for (int k = 0; k < 32; k++) {
            const float a0 = Ws[ty * 4 + 0][k], a1 = Ws[ty * 4 + 1][k];
            const float a2 = Ws[ty * 4 + 2][k], a3 = Ws[ty * 4 + 3][k];
            const float p0 = Ps[tx * 4 + 0][k], p1 = Ps[tx * 4 + 1][k];
            const float p2 = Ps[tx * 4 + 2][k], p3 = Ps[tx * 4 + 3][k];
            acc[0][0] += a0 * p0; acc[0][1] += a0 * p1; acc[0][2] += a0 * p2; acc[0][3] += a0 * p3;
            acc[1][0] += a1 * p0; acc[1][1] += a1 * p1; acc[1][2] += a1 * p2; acc[1][3] += a1 * p3;
            acc[2][0] += a2 * p0; acc[2][1] += a2 * p1; acc[2][2] += a2 * p2; acc[2][3] += a2 * p3;
            acc[3][0] += a3 * p0; acc[3][1] += a3 * p1; acc[3][2] += a3 * p2; acc[3][3] += a3 * p3;
        }
        __syncthreads();
    }

#pragma unroll
    for (int oi = 0; oi < 4; oi++) {
        const int o = o0 + ty * 4 + oi;
        const float inv  = gamma[o] / sqrtf(rvar[o] + 1e-5f);
        const float bias = fmaf(-rmean[o], inv, beta[o]);  // beta - rmean*inv
        float vs[4];
#pragma unroll
        for (int ji = 0; ji < 4; ji++) {
            const float y = fmaf(acc[oi][ji], inv, bias);
            vs[ji] = (y >= 0.0f) ? y : 0.2f * y;
        }
        float4 vv = make_float4(vs[0], vs[1], vs[2], vs[3]);
        *reinterpret_cast<float4*>(out + (size_t)(b * COUTc + o) * NPc + j0 + tx * 4) = vv;
    }
}

// ---------------------------------------------------------------------------
extern "C" void kernel_launch(void* const* d_in, const int* in_sizes, int n_in,
                              void* d_out, int out_size) {
    const float* xyz    = (const float*)d_in[0];
    const float* feats  = (const float*)d_in[1];
    const float* conv_w = (const float*)d_in[2];
    const float* gamma  = (const float*)d_in[3];
    const float* beta   = (const float*)d_in[4];
    const float* rmean  = (const float*)d_in[5];
    const float* rvar   = (const float*)d_in[6];
    float* out = (float*)d_out;

    transpose_kernel<<<dim3(Nc / 32, CINc / 32, Bc), dim3(32, 8)>>>(feats);
    fps_kernel<<<Bc, 512>>>(xyz);
    pool_kernel<<<Bc * NPc, 128>>>(xyz);
    gemm_bn_relu_kernel<<<dim3(NPc / 64, COUTc / 64, Bc), 256>>>(
        conv_w, gamma, beta, rmean, rvar, out);
}

// round 6
// speedup vs baseline: 1.5455x; 1.0329x over previous
#include <cuda_runtime.h>

#define Bc 4
#define Nc 8192
#define NPc 2048
#define NSc 32
#define CINc 128
#define COUTc 256

// Scratch (no cudaMalloc allowed): device globals
__device__ int   g_fidx[Bc * NPc];
__device__ float g_featsT[(size_t)Bc * Nc * CINc];    // [B, N, CIN]  16 MB
__device__ float g_pooledT[(size_t)Bc * NPc * CINc];  // [B, NP, CIN]  4 MB

// ---------------- packed f32x2 helpers (sm_103a) ----------------
// NOTE: only add/mul/fma exist in f32x2 form; min/max do NOT (ptxas rejects).
typedef unsigned long long ull;

__device__ __forceinline__ ull f2pack(float lo, float hi) {
    ull r; asm("mov.b64 %0, {%1, %2};" : "=l"(r) : "f"(lo), "f"(hi)); return r;
}
__device__ __forceinline__ float2 f2unpack(ull v) {
    float2 f; asm("mov.b64 {%0, %1}, %2;" : "=f"(f.x), "=f"(f.y) : "l"(v)); return f;
}
__device__ __forceinline__ ull f2add(ull a, ull b) {
    ull r; asm("add.rn.f32x2 %0, %1, %2;" : "=l"(r) : "l"(a), "l"(b)); return r;
}
__device__ __forceinline__ ull f2mul(ull a, ull b) {
    ull r; asm("mul.rn.f32x2 %0, %1, %2;" : "=l"(r) : "l"(a), "l"(b)); return r;
}
__device__ __forceinline__ ull f2fma(ull a, ull b, ull c) {
    ull r; asm("fma.rn.f32x2 %0, %1, %2, %3;" : "=l"(r) : "l"(a), "l"(b), "l"(c)); return r;
}

__device__ __forceinline__ unsigned expand6(unsigned v) {  // 6 bits -> every 3rd bit
    v = (v * 0x00010001u) & 0xFF0000FFu;
    v = (v * 0x00000101u) & 0x0F00F00Fu;
    v = (v * 0x00000011u) & 0xC30C30C3u;
    v = (v * 0x00000005u) & 0x49249249u;
    return v;
}

// ---------------------------------------------------------------------------
// 1) Furthest point sampling with EXACT bounding-sphere pruning.
//    One 512-thread block per batch, 16 points/thread.
//    Prep: 18-bit Morton key (6 bits/axis) << 13 | original index packed in a
//    u32, bitonic-sorted in shared -> thread t owns 16 spatially-contiguous
//    points; AABB center + inflated radius r per thread.
//    Per iteration:
//      - stage 1: warp REDUX.MAX on value bits; only lanes with bv==best
//        compute the lowest matching ORIGINAL index; REDUX.MIN
//      - one __syncthreads; stage 2: all warps redundantly reduce 16 pairs
//      - prune: if d2(q,center) >= ((r + sqrt(rm)) * 1.0005)^2 then every new
//        distance >= every mind[p]  =>  fminf is a no-op for all 16 points:
//        skip the update entirely (bit-exact; margins >> fp error in bound)
//      - else packed f32x2 distance + scalar fmin + fused running max
//    All per-lane arithmetic and tie-breaks (lowest original index) identical
//    to the unpruned kernel -> identical selected indices.
// ---------------------------------------------------------------------------
__global__ void __launch_bounds__(512, 1) fps_kernel(const float* __restrict__ xyz) {
    const int b = blockIdx.x;
    const float* xb = xyz + (size_t)b * Nc * 3;
    const int t = threadIdx.x;
    const int lane = t & 31;

    __shared__ unsigned skey[Nc];        // 32 KB: (morton18 << 13) | idx13
    __shared__ unsigned sv[2][16];
    __shared__ int      si[2][16];

    // ---- phase A: build sort keys ----
#pragma unroll
    for (int r = 0; r < 16; r++) {
        const int i = t + r * 512;
        const float x = xb[3 * i], y = xb[3 * i + 1], z = xb[3 * i + 2];
        unsigned cx = min(63u, (unsigned)(x * 64.0f));
        unsigned cy = min(63u, (unsigned)(y * 64.0f));
        unsigned cz = min(63u, (unsigned)(z * 64.0f));
        const unsigned m = (expand6(cz) << 2) | (expand6(cy) << 1) | expand6(cx);
        skey[i] = (m << 13) | (unsigned)i;
    }
    __syncthreads();

    // ---- phase B: bitonic sort (8192 u32) ----
    for (unsigned ksz = 2; ksz <= (unsigned)Nc; ksz <<= 1) {
        for (unsigned j = ksz >> 1; j > 0; j >>= 1) {
#pragma unroll 4
            for (int r = 0; r < 16; r++) {
                const int i = t + r * 512;
                const int p = i ^ (int)j;
                if (p > i) {
                    const unsigned a = skey[i], c = skey[p];
                    const bool up = ((i & (int)ksz) == 0);
                    if (up ? (a > c) : (a < c)) { skey[i] = c; skey[p] = a; }
                }
            }
            __syncthreads();
        }
    }

    // ---- phase C: gather owned points, bounding sphere ----
    ull pxp[8], pyp[8], pzp[8];
    unsigned oidxp[8];           // two u16 original indices per reg
    float cx_, cy_, cz_, rad;
    {
        float px[16], py[16], pz[16];
#pragma unroll
        for (int p = 0; p < 16; p++) {
            const unsigned oi = skey[16 * t + p] & 8191u;
            px[p] = xb[3 * oi];
            py[p] = xb[3 * oi + 1];
            pz[p] = xb[3 * oi + 2];
            if (p & 1) oidxp[p >> 1] |= oi << 16;
            else       oidxp[p >> 1]  = oi;
        }
#pragma unroll
        for (int i = 0; i < 8; i++) {
            pxp[i] = f2pack(px[2 * i], px[2 * i + 1]);
            pyp[i] = f2pack(py[2 * i], py[2 * i + 1]);
            pzp[i] = f2pack(pz[2 * i], pz[2 * i + 1]);
        }
        float mnx = px[0], mxx = px[0], mny = py[0], mxy = py[0], mnz = pz[0], mxz = pz[0];
#pragma unroll
        for (int p = 1; p < 16; p++) {
            mnx = fminf(mnx, px[p]); mxx = fmaxf(mxx, px[p]);
            mny = fminf(mny, py[p]); mxy = fmaxf(mxy, py[p]);
            mnz = fminf(mnz, pz[p]); mxz = fmaxf(mxz, pz[p]);
        }
        cx_ = 0.5f * (mnx + mxx); cy_ = 0.5f * (mny + mxy); cz_ = 0.5f * (mnz + mxz);
        float r2 = 0.0f;
#pragma unroll
        for (int p = 0; p < 16; p++) {
            const float dx = px[p] - cx_, dy = py[p] - cy_, dz = pz[p] - cz_;
            float d = dx * dx; d = fmaf(dy, dy, d); d = fmaf(dz, dz, d);
            r2 = fmaxf(r2, d);
        }
        rad = sqrtf(r2) * 1.001f + 1e-5f;   // inflated: covers fp error in bound
    }

    // ---- phase D: init distances to original point 0 ----
    float mind[16];
    float bv;
    {
        const float qx = xb[0], qy = xb[1], qz = xb[2];
        const ull nqx = f2pack(-qx, -qx), nqy = f2pack(-qy, -qy), nqz = f2pack(-qz, -qz);
        float rm = 0.0f;
#pragma unroll
        for (int i = 0; i < 8; i++) {
            ull dx = f2add(pxp[i], nqx);
            ull dy = f2add(pyp[i], nqy);
            ull dz = f2add(pzp[i], nqz);
            ull d = f2mul(dx, dx); d = f2fma(dy, dy, d); d = f2fma(dz, dz, d);
            const float2 dd = f2unpack(d);
            mind[2 * i]     = dd.x;
            mind[2 * i + 1] = dd.y;
            rm = fmaxf(rm, fmaxf(dd.x, dd.y));
        }
        bv = rm;
    }
    if (t == 0) g_fidx[b * NPc] = 0;

    // ---- phase E: main loop ----
    for (int k = 1; k < NPc; k++) {
        // stage 1: warp max value (distances >= 0: uint order == float order)
        const unsigned best = __reduce_max_sync(0xffffffffu, __float_as_uint(bv));
        int cand = 0x7fffffff;
        if (__float_as_uint(bv) == best) {   // only winning lanes do the scan
#pragma unroll
            for (int p = 0; p < 16; p++)
                if (__float_as_uint(mind[p]) == best) {
                    const int oi = (int)((oidxp[p >> 1] >> ((p & 1) * 16)) & 0xffffu);
                    cand = min(cand, oi);
                }
        }
        const int widx = __reduce_min_sync(0xffffffffu, cand);

        const int s = k & 1;
        if (lane == 0) { sv[s][t >> 5] = best; si[s][t >> 5] = widx; }
        __syncthreads();

        // stage 2: all warps redundantly reduce the 16 (value, index) pairs
        const unsigned wv = sv[s][lane & 15];
        const int      wi = si[s][lane & 15];
        const unsigned gbest = __reduce_max_sync(0xffffffffu, wv);
        const int gcand = (wv == gbest) ? wi : 0x7fffffff;
        const int w = __reduce_min_sync(0xffffffffu, gcand);
        if (t == 0) g_fidx[b * NPc + k] = w;

        // broadcast load of winner coords (L1-resident, same-address broadcast)
        const float qx = xb[w * 3], qy = xb[w * 3 + 1], qz = xb[w * 3 + 2];

        // exact prune: if every new distance >= every mind[p], skip the update
        const float ex = cx_ - qx, ey = cy_ - qy, ez = cz_ - qz;
        float dqc2 = ex * ex; dqc2 = fmaf(ey, ey, dqc2); dqc2 = fmaf(ez, ez, dqc2);
        float sthr = (rad + sqrtf(bv)) * 1.0005f;
        if (dqc2 < sthr * sthr) {
            const ull nqx = f2pack(-qx, -qx), nqy = f2pack(-qy, -qy), nqz = f2pack(-qz, -qz);
            float rm = 0.0f;
#pragma unroll
            for (int i = 0; i < 8; i++) {
                ull dx = f2add(pxp[i], nqx);
                ull dy = f2add(pyp[i], nqy);
                ull dz = f2add(pzp[i], nqz);
                ull d = f2mul(dx, dx); d = f2fma(dy, dy, d); d = f2fma(dz, dz, d);
                const float2 dd = f2unpack(d);
                const float m0 = fminf(mind[2 * i],     dd.x);
                const float m1 = fminf(mind[2 * i + 1], dd.y);
                mind[2 * i]     = m0;
                mind[2 * i + 1] = m1;
                rm = fmaxf(rm, fmaxf(m0, m1));
            }
            bv = rm;
        }
    }
}

// ---------------------------------------------------------------------------
// 2) Transpose feats [B, CIN, N] -> featsT [B, N, CIN] for coalesced gathers
// ---------------------------------------------------------------------------
__global__ void __launch_bounds__(256) transpose_kernel(const float* __restrict__ feats) {
    __shared__ float tile[32][33];
    const int b  = blockIdx.z;
    const int n0 = blockIdx.x * 32;
    const int c0 = blockIdx.y * 32;
    const int x = threadIdx.x, y = threadIdx.y;
#pragma unroll
    for (int r = 0; r < 32; r += 8)
        tile[y + r][x] = feats[(size_t)(b * CINc + c0 + y + r) * Nc + n0 + x];
    __syncthreads();
#pragma unroll
    for (int r = 0; r < 32; r += 8)
        g_featsT[(size_t)(b * Nc + n0 + y + r) * CINc + c0 + x] = tile[x][y + r];
}

// ---------------------------------------------------------------------------
// 3) Ball query (warp 0, ballot-compaction with early exit) + gather + maxpool
//    (128 channel-threads). One block per query point.
// ---------------------------------------------------------------------------
__global__ void __launch_bounds__(128) pool_kernel(const float* __restrict__ xyz) {
    const int b = blockIdx.x >> 11;     // / NPc
    const int j = blockIdx.x & (NPc - 1);
    __shared__ int sidx[NSc];
    const int tid = threadIdx.x;

    if (tid < 32) {
        const float* xb = xyz + (size_t)b * Nc * 3;
        const int fi = g_fidx[b * NPc + j];
        const float qx = xb[fi * 3], qy = xb[fi * 3 + 1], qz = xb[fi * 3 + 2];
        const float R2 = 0.04f;  // float(0.04): matches JAX weak-typed 0.2*0.2 promotion
        int count = 0;
        for (int base = 0; base < Nc && count < NSc; base += 32) {
            const int i = base + tid;
            float dx = xb[i * 3] - qx, dy = xb[i * 3 + 1] - qy, dz = xb[i * 3 + 2] - qz;
            float d = dx * dx; d = fmaf(dy, dy, d); d = fmaf(dz, dz, d);
            const bool in = d < R2;
            const unsigned m = __ballot_sync(0xffffffffu, in);
            const int pos = count + __popc(m & ((1u << tid) - 1u));
            if (in && pos < NSc) sidx[pos] = i;
            count += __popc(m);
        }
        __syncwarp();
        // pad with first neighbor (count >= 1 always: query pt is in its own ball)
        const int first = (count > 0) ? sidx[0] : 0;
        for (int s = count + tid; s < NSc; s += 32) sidx[s] = first;
    }
    __syncthreads();

    const float* ft = g_featsT + (size_t)b * Nc * CINc;
    const int c = tid;  // 128 threads == CIN channels
    float m = __int_as_float(0xff800000);  // -inf
#pragma unroll
    for (int s = 0; s < NSc; s++)
        m = fmaxf(m, ft[(size_t)sidx[s] * CINc + c]);
    g_pooledT[((size_t)(b * NPc + j)) * CINc + c] = m;
}

// ---------------------------------------------------------------------------
// 4) out[b,o,j] = lrelu( (W[o,:] . pooledT[b,j,:]) * inv[o] + (beta - rmean*inv)[o] )
//    64x64 shared-tiled SIMT GEMM, 4x4 per-thread microtile, float4 stores.
// ---------------------------------------------------------------------------
__global__ void __launch_bounds__(256) gemm_bn_relu_kernel(
    const float* __restrict__ W,
    const float* __restrict__ gamma, const float* __restrict__ beta,
    const float* __restrict__ rmean, const float* __restrict__ rvar,
    float* __restrict__ out)
{
    __shared__ float Ws[64][33];
    __shared__ float Ps[64][33];
    const int b  = blockIdx.z;
    const int j0 = blockIdx.x * 64;
    const int o0 = blockIdx.y * 64;
    const int tid = threadIdx.x;
    const int tx = tid & 15, ty = tid >> 4;

    const float* Pbase = g_pooledT + ((size_t)b * NPc + j0) * CINc;

    float acc[4][4];
#pragma unroll
    for (int i = 0; i < 4; i++)
#pragma unroll
        for (int jj = 0; jj < 4; jj++) acc[i][jj] = 0.0f;

    for (int k0 = 0; k0 < CINc; k0 += 32) {
#pragma unroll
        for (int l = 0; l < 8; l++) {
            const int idx = tid + l * 256;
            const int r = idx >> 5, kk = idx & 31;
            Ws[r][kk] = W[(size_t)(o0 + r) * CINc + k0 + kk];
            Ps[r][kk] = Pbase[(size_t)r * CINc + k0 + kk];
        }
        __syncthreads();
#pragma unroll
        for (int k = 0; k < 32; k++) {
            const float a0 = Ws[ty * 4 + 0][k], a1 = Ws[ty * 4 + 1][k];
            const float a2 = Ws[ty * 4 + 2][k], a3 = Ws[ty * 4 + 3][k];
            const float p0 = Ps[tx * 4 + 0][k], p1 = Ps[tx * 4 + 1][k];
            const float p2 = Ps[tx * 4 + 2][k], p3 = Ps[tx * 4 + 3][k];
            acc[0][0] += a0 * p0; acc[0][1] += a0 * p1; acc[0][2] += a0 * p2; acc[0][3] += a0 * p3;
            acc[1][0] += a1 * p0; acc[1][1] += a1 * p1; acc[1][2] += a1 * p2; acc[1][3] += a1 * p3;
            acc[2][0] += a2 * p0; acc[2][1] += a2 * p1; acc[2][2] += a2 * p2; acc[2][3] += a2 * p3;
            acc[3][0] += a3 * p0; acc[3][1] += a3 * p1; acc[3][2] += a3 * p2; acc[3][3] += a3 * p3;
        }
        __syncthreads();
    }

#pragma unroll
    for (int oi = 0; oi < 4; oi++) {
        const int o = o0 + ty * 4 + oi;
        const float inv  = gamma[o] / sqrtf(rvar[o] + 1e-5f);
        const float bias = fmaf(-rmean[o], inv, beta[o]);  // beta - rmean*inv
        float vs[4];
#pragma unroll
        for (int ji = 0; ji < 4; ji++) {
            const float y = fmaf(acc[oi][ji], inv, bias);
            vs[ji] = (y >= 0.0f) ? y : 0.2f * y;
        }
        float4 vv = make_float4(vs[0], vs[1], vs[2], vs[3]);
        *reinterpret_cast<float4*>(out + (size_t)(b * COUTc + o) * NPc + j0 + tx * 4) = vv;
    }
}

// ---------------------------------------------------------------------------
extern "C" void kernel_launch(void* const* d_in, const int* in_sizes, int n_in,
                              void* d_out, int out_size) {
    const float* xyz    = (const float*)d_in[0];
    const float* feats  = (const float*)d_in[1];
    const float* conv_w = (const float*)d_in[2];
    const float* gamma  = (const float*)d_in[3];
    const float* beta   = (const float*)d_in[4];
    const float* rmean  = (const float*)d_in[5];
    const float* rvar   = (const float*)d_in[6];
    float* out = (float*)d_out;

    transpose_kernel<<<dim3(Nc / 32, CINc / 32, Bc), dim3(32, 8)>>>(feats);
    fps_kernel<<<Bc, 512>>>(xyz);
    pool_kernel<<<Bc * NPc, 128>>>(xyz);
    gemm_bn_relu_kernel<<<dim3(NPc / 64, COUTc / 64, Bc), 256>>>(
        conv_w, gamma, beta, rmean, rvar, out);
}